// round 4
// baseline (speedup 1.0000x reference)
#include <cuda_runtime.h>
#include <cstdint>

// ---------------------------------------------------------------------------
// GaussianNNHeightmapEncoder
//   x: [B, 4096] -> reshape [B, 64, 64]
//   4x: h = lrelu( K_l @ (h @ W_l^T + b_l) )   (K_l row-stochastic => bias commutes)
//   flatten -> lrelu(h @ wm0^T + bm0) -> lrelu(@ wm1^T + bm1) -> [B, 60]
// Inputs (metadata order):
//   0:x 1:w0 2:b0 3:s0 4:w1 5:b1 6:s1 7:w2 8:b2 9:s2 10:w3 11:b3 12:s3
//   13:wm0 14:bm0 15:wm1 16:bm1
// ---------------------------------------------------------------------------

#define MAXB 16384

__device__ float g_K[4 * 64 * 64];                 // per-layer normalized kernel, row-major
__device__ float g_h[(size_t)MAXB * 4096];         // scratch: final gauss features

__device__ __forceinline__ float lrelu(float v) { return fmaxf(v, 0.01f * v); }

// ---------------------------------------------------------------------------
// Kernel P: precompute normalized Gaussian kernels (4 x 64 x 64)
// ---------------------------------------------------------------------------
__global__ void kprep_kernel(const float* __restrict__ s0, const float* __restrict__ s1,
                             const float* __restrict__ s2, const float* __restrict__ s3) {
    int tid = threadIdx.x;
    if (tid >= 256) return;
    int l = tid >> 6, i = tid & 63;
    float sig = (l == 0) ? s0[0] : (l == 1) ? s1[0] : (l == 2) ? s2[0] : s3[0];
    float inv = 1.0f / (2.0f * sig * sig);
    float sum = 0.0f;
    for (int j = 0; j < 64; j++) {
        float d = (float)(i - j);
        sum += expf(-d * d * inv);
    }
    float r = 1.0f / fmaxf(sum, 1e-12f);
    float* dst = g_K + (l * 64 + i) * 64;
    for (int j = 0; j < 64; j++) {
        float d = (float)(i - j);
        dst[j] = expf(-d * d * inv) * r;
    }
}

// ---------------------------------------------------------------------------
// Kernel B: fused 4 Gaussian layers. 8 samples / CTA, 64 threads per sample
// (thread = output row i). State buffers are column-major [c][64] in smem so
// per-thread column accesses are conflict-free and j-contiguous reads are
// float4-vectorizable.
// ---------------------------------------------------------------------------

// smem layout (floats):
#define OFF_KR   0        // K row-major, stride 80 (pad for conflict-free float4 row reads)
#define OFF_W0   5120     // 8x64
#define OFF_W1   5632     // 16x8
#define OFF_W2   5760     // 32x16
#define OFF_W3   6272     // 64x32
#define OFF_B0   8320
#define OFF_B1   8328
#define OFF_B2   8344
#define OFF_B3   8376
#define OFF_SA   8448     // per-sample: A(2048) + Bb(2048)
#define GAUSS_SMEM_FLOATS (OFF_SA + 8 * 4096)     // 41216 floats = 164864 B

__device__ __forceinline__ void stage_k(float* __restrict__ KR, int l, int tid) {
    const float* __restrict__ src = g_K + l * 4096;
#pragma unroll
    for (int t = 0; t < 8; t++) {
        int idx = tid + t * 512;                  // 0..4095
        KR[(idx >> 6) * 80 + (idx & 63)] = src[idx];
    }
}

// dst[c][i] = (lrelu?) sum_j K[i][j] * src[c][j]
template <int CIN, bool LRELU>
__device__ __forceinline__ void kmul(const float* __restrict__ KR, const float* __restrict__ src,
                                     float* __restrict__ dst, int i) {
    constexpr int CC = (CIN < 16) ? CIN : 16;
#pragma unroll
    for (int c0 = 0; c0 < CIN; c0 += CC) {
        float acc[CC];
#pragma unroll
        for (int c = 0; c < CC; c++) acc[c] = 0.0f;
#pragma unroll 4
        for (int j4 = 0; j4 < 64; j4 += 4) {
            float4 kv = *(const float4*)&KR[i * 80 + j4];
#pragma unroll
            for (int c = 0; c < CC; c++) {
                float4 av = *(const float4*)&src[(c0 + c) * 64 + j4];
                acc[c] = fmaf(kv.x, av.x, fmaf(kv.y, av.y, fmaf(kv.z, av.z, fmaf(kv.w, av.w, acc[c]))));
            }
        }
#pragma unroll
        for (int c = 0; c < CC; c++) {
            float v = acc[c];
            if (LRELU) v = lrelu(v);
            dst[(c0 + c) * 64 + i] = v;
        }
    }
}

// dst[o][i] = lrelu( b[o] + sum_c src[c][i] * W[o][c] )
template <int CIN, int COUT>
__device__ __forceinline__ void wmul(const float* __restrict__ Ws, const float* __restrict__ bs,
                                     const float* __restrict__ src, float* __restrict__ dst, int i) {
    constexpr int OC = (COUT < 16) ? COUT : 16;
#pragma unroll
    for (int o0 = 0; o0 < COUT; o0 += OC) {
        float acc[OC];
#pragma unroll
        for (int o = 0; o < OC; o++) acc[o] = bs[o0 + o];
#pragma unroll 2
        for (int c4 = 0; c4 < CIN; c4 += 4) {
            float z0 = src[(c4 + 0) * 64 + i];
            float z1 = src[(c4 + 1) * 64 + i];
            float z2 = src[(c4 + 2) * 64 + i];
            float z3 = src[(c4 + 3) * 64 + i];
#pragma unroll
            for (int o = 0; o < OC; o++) {
                float4 wv = *(const float4*)&Ws[(o0 + o) * CIN + c4];
                acc[o] = fmaf(z0, wv.x, fmaf(z1, wv.y, fmaf(z2, wv.z, fmaf(z3, wv.w, acc[o]))));
            }
        }
#pragma unroll
        for (int o = 0; o < OC; o++) dst[(o0 + o) * 64 + i] = lrelu(acc[o]);
    }
}

// Same as wmul but stores the (contiguous) per-thread row straight to gmem.
template <int CIN, int COUT>
__device__ __forceinline__ void wmul_gmem(const float* __restrict__ Ws, const float* __restrict__ bs,
                                          const float* __restrict__ src, float* __restrict__ gdst,
                                          int i, bool active) {
#pragma unroll
    for (int o0 = 0; o0 < COUT; o0 += 16) {
        float acc[16];
#pragma unroll
        for (int o = 0; o < 16; o++) acc[o] = bs[o0 + o];
#pragma unroll 2
        for (int c4 = 0; c4 < CIN; c4 += 4) {
            float z0 = src[(c4 + 0) * 64 + i];
            float z1 = src[(c4 + 1) * 64 + i];
            float z2 = src[(c4 + 2) * 64 + i];
            float z3 = src[(c4 + 3) * 64 + i];
#pragma unroll
            for (int o = 0; o < 16; o++) {
                float4 wv = *(const float4*)&Ws[(o0 + o) * CIN + c4];
                acc[o] = fmaf(z0, wv.x, fmaf(z1, wv.y, fmaf(z2, wv.z, fmaf(z3, wv.w, acc[o]))));
            }
        }
        if (active) {
#pragma unroll
            for (int q = 0; q < 4; q++) {
                float4 v;
                v.x = lrelu(acc[q * 4 + 0]);
                v.y = lrelu(acc[q * 4 + 1]);
                v.z = lrelu(acc[q * 4 + 2]);
                v.w = lrelu(acc[q * 4 + 3]);
                *(float4*)&gdst[o0 + q * 4] = v;
            }
        }
    }
}

__global__ __launch_bounds__(512, 1) void gauss_kernel(
    const float* __restrict__ x,
    const float* __restrict__ w0, const float* __restrict__ b0,
    const float* __restrict__ w1, const float* __restrict__ b1,
    const float* __restrict__ w2, const float* __restrict__ b2,
    const float* __restrict__ w3, const float* __restrict__ b3,
    int B) {
    extern __shared__ float sm[];
    float* KR  = sm + OFF_KR;
    float* W0s = sm + OFF_W0;
    float* W1s = sm + OFF_W1;
    float* W2s = sm + OFF_W2;
    float* W3s = sm + OFF_W3;
    float* b0s = sm + OFF_B0;
    float* b1s = sm + OFF_B1;
    float* b2s = sm + OFF_B2;
    float* b3s = sm + OFF_B3;

    int tid = threadIdx.x;

    // Stage all weights once + K for layer 0.
    for (int t = tid; t < 512;  t += 512) W0s[t] = w0[t];
    for (int t = tid; t < 128;  t += 512) W1s[t] = w1[t];
    for (int t = tid; t < 512;  t += 512) W2s[t] = w2[t];
    for (int t = tid; t < 2048; t += 512) W3s[t] = w3[t];
    if (tid < 8)  b0s[tid] = b0[tid];
    if (tid < 16) b1s[tid] = b1[tid];
    if (tid < 32) b2s[tid] = b2[tid];
    if (tid < 64) b3s[tid] = b3[tid];
    stage_k(KR, 0, tid);
    __syncthreads();

    int s = tid >> 6, i = tid & 63;
    long b = (long)blockIdx.x * 8 + s;
    bool active = (b < B);
    float* A  = sm + OFF_SA + s * 4096;
    float* Bb = A + 2048;

    // ---- L0 (ref order): XP = X @ W0^T + b0 ; A = lrelu(K0 @ XP) ----
    {
        const float* xrow = x + (active ? b * 4096 + (long)i * 64 : 0);
        float acc[8];
#pragma unroll
        for (int o = 0; o < 8; o++) acc[o] = b0s[o];
#pragma unroll
        for (int half = 0; half < 2; half++) {
            float4 xr[8];
#pragma unroll
            for (int q = 0; q < 8; q++) {
                xr[q] = active ? *(const float4*)&xrow[half * 32 + q * 4]
                               : make_float4(0.f, 0.f, 0.f, 0.f);
            }
#pragma unroll
            for (int o = 0; o < 8; o++) {
#pragma unroll
                for (int q = 0; q < 8; q++) {
                    float4 wv = *(const float4*)&W0s[o * 64 + half * 32 + q * 4];
                    acc[o] = fmaf(xr[q].x, wv.x, fmaf(xr[q].y, wv.y,
                             fmaf(xr[q].z, wv.z, fmaf(xr[q].w, wv.w, acc[o]))));
                }
            }
        }
#pragma unroll
        for (int o = 0; o < 8; o++) Bb[o * 64 + i] = acc[o];
    }
    __syncthreads();
    kmul<8, true>(KR, Bb, A, i);     // A = lrelu(K0 @ XP)

    // ---- L1 (alt order): A = lrelu((K1 @ A) @ W1^T + b1) ----
    __syncthreads();
    stage_k(KR, 1, tid);
    __syncthreads();
    kmul<8, false>(KR, A, Bb, i);
    wmul<8, 16>(W1s, b1s, Bb, A, i);

    // ---- L2 ----
    __syncthreads();
    stage_k(KR, 2, tid);
    __syncthreads();
    kmul<16, false>(KR, A, Bb, i);
    wmul<16, 32>(W2s, b2s, Bb, A, i);

    // ---- L3 (writes straight to g_h) ----
    __syncthreads();
    stage_k(KR, 3, tid);
    __syncthreads();
    kmul<32, false>(KR, A, Bb, i);
    wmul_gmem<32, 64>(W3s, b3s, Bb, g_h + (active ? ((size_t)b * 4096 + (size_t)i * 64) : 0), i, active);
}

// ---------------------------------------------------------------------------
// Kernel C: [B,4096] @ wm0^T (+bm0, lrelu) then @ wm1^T (+bm1, lrelu) -> out
// Tile: 64 samples x 80 outs per CTA, 256 threads (16x16 grid, 4x5 microtile).
// ---------------------------------------------------------------------------
#define AS_STRIDE 68
#define BS_STRIDE 81
#define C_OFF_AS  0
#define C_OFF_BS  (64 * AS_STRIDE)                 // 4352
#define C_OFF_W1  (C_OFF_BS + 64 * BS_STRIDE)      // 4352 + 5184 = 9536
#define COMPRESS_SMEM_FLOATS (C_OFF_W1 + 4800)     // 14336 floats = 57344 B

__global__ __launch_bounds__(256, 3) void compress_kernel(
    const float* __restrict__ wm0, const float* __restrict__ bm0,
    const float* __restrict__ wm1, const float* __restrict__ bm1,
    float* __restrict__ out, int B) {
    extern __shared__ float sm[];
    float* As  = sm + C_OFF_AS;
    float* Bs  = sm + C_OFF_BS;
    float* W1s = sm + C_OFF_W1;

    int tid = threadIdx.x;
    long m0 = (long)blockIdx.x * 64;

    for (int t = tid; t < 4800; t += 256) W1s[t] = wm1[t];

    int tc = tid & 15, tr = tid >> 4;
    float acc[4][5];
#pragma unroll
    for (int r = 0; r < 4; r++)
#pragma unroll
        for (int j = 0; j < 5; j++) acc[r][j] = 0.0f;

    for (int k0 = 0; k0 < 4096; k0 += 64) {
        __syncthreads();
        // Load A tile (64 samples x 64 k), coalesced gmem, padded smem
#pragma unroll
        for (int it = 0; it < 4; it++) {
            int t = tid + it * 256;            // 0..1023
            int k4 = (t & 15) * 4;
            int m = t >> 4;
            float4 v = make_float4(0.f, 0.f, 0.f, 0.f);
            long gm = m0 + m;
            if (gm < B) v = *(const float4*)&g_h[(size_t)gm * 4096 + k0 + k4];
            *(float4*)&As[m * AS_STRIDE + k4] = v;
        }
        // Load B tile (wm0, transposed into [k][o])
#pragma unroll
        for (int it = 0; it < 5; it++) {
            int t = tid + it * 256;            // 0..1279
            int k4 = (t & 15) * 4;
            int o = t >> 4;                    // 0..79
            float4 v = *(const float4*)&wm0[(size_t)o * 4096 + k0 + k4];
            Bs[(k4 + 0) * BS_STRIDE + o] = v.x;
            Bs[(k4 + 1) * BS_STRIDE + o] = v.y;
            Bs[(k4 + 2) * BS_STRIDE + o] = v.z;
            Bs[(k4 + 3) * BS_STRIDE + o] = v.w;
        }
        __syncthreads();
#pragma unroll 4
        for (int k = 0; k < 64; k++) {
            float a0 = As[(tr * 4 + 0) * AS_STRIDE + k];
            float a1 = As[(tr * 4 + 1) * AS_STRIDE + k];
            float a2 = As[(tr * 4 + 2) * AS_STRIDE + k];
            float a3 = As[(tr * 4 + 3) * AS_STRIDE + k];
            float bj[5];
#pragma unroll
            for (int j = 0; j < 5; j++) bj[j] = Bs[k * BS_STRIDE + tc * 5 + j];
#pragma unroll
            for (int j = 0; j < 5; j++) {
                acc[0][j] = fmaf(a0, bj[j], acc[0][j]);
                acc[1][j] = fmaf(a1, bj[j], acc[1][j]);
                acc[2][j] = fmaf(a2, bj[j], acc[2][j]);
                acc[3][j] = fmaf(a3, bj[j], acc[3][j]);
            }
        }
    }
    __syncthreads();

    // h1 = lrelu(acc + bm0), stored [64][81] overlaying As/Bs
    float* h1 = sm;
#pragma unroll
    for (int r = 0; r < 4; r++) {
#pragma unroll
        for (int j = 0; j < 5; j++) {
            float v = acc[r][j] + __ldg(&bm0[tc * 5 + j]);
            h1[(tr * 4 + r) * BS_STRIDE + tc * 5 + j] = lrelu(v);
        }
    }
    __syncthreads();

    // Second layer: out[m][o2] = lrelu(bm1[o2] + sum_c h1[m][c] * wm1[o2][c])
    for (int ii = 0; ii < 15; ii++) {
        int idx = tid + ii * 256;              // < 3840
        int m = idx & 63, o2 = idx >> 6;       // o2 < 60
        float a = __ldg(&bm1[o2]);
#pragma unroll 4
        for (int c4 = 0; c4 < 80; c4 += 4) {
            float4 wv = *(const float4*)&W1s[o2 * 80 + c4];
            a = fmaf(h1[m * BS_STRIDE + c4 + 0], wv.x,
                fmaf(h1[m * BS_STRIDE + c4 + 1], wv.y,
                fmaf(h1[m * BS_STRIDE + c4 + 2], wv.z,
                fmaf(h1[m * BS_STRIDE + c4 + 3], wv.w, a))));
        }
        long gm = m0 + m;
        if (gm < B) out[gm * 60 + o2] = lrelu(a);
    }
}

// ---------------------------------------------------------------------------
extern "C" void kernel_launch(void* const* d_in, const int* in_sizes, int n_in,
                              void* d_out, int out_size) {
    const float* x   = (const float*)d_in[0];
    const float* w0  = (const float*)d_in[1];
    const float* b0  = (const float*)d_in[2];
    const float* s0  = (const float*)d_in[3];
    const float* w1  = (const float*)d_in[4];
    const float* b1  = (const float*)d_in[5];
    const float* s1  = (const float*)d_in[6];
    const float* w2  = (const float*)d_in[7];
    const float* b2  = (const float*)d_in[8];
    const float* s2  = (const float*)d_in[9];
    const float* w3  = (const float*)d_in[10];
    const float* b3  = (const float*)d_in[11];
    const float* s3  = (const float*)d_in[12];
    const float* wm0 = (const float*)d_in[13];
    const float* bm0 = (const float*)d_in[14];
    const float* wm1 = (const float*)d_in[15];
    const float* bm1 = (const float*)d_in[16];

    int B = in_sizes[0] / 4096;
    if (B > MAXB) B = MAXB;

    cudaFuncSetAttribute((const void*)gauss_kernel,
                         cudaFuncAttributeMaxDynamicSharedMemorySize,
                         GAUSS_SMEM_FLOATS * 4);
    cudaFuncSetAttribute((const void*)compress_kernel,
                         cudaFuncAttributeMaxDynamicSharedMemorySize,
                         COMPRESS_SMEM_FLOATS * 4);

    kprep_kernel<<<1, 256>>>(s0, s1, s2, s3);
    gauss_kernel<<<(B + 7) / 8, 512, GAUSS_SMEM_FLOATS * 4>>>(
        x, w0, b0, w1, b1, w2, b2, w3, b3, B);
    compress_kernel<<<(B + 63) / 64, 256, COMPRESS_SMEM_FLOATS * 4>>>(
        wm0, bm0, wm1, bm1, (float*)d_out, B);
}

// round 8
// speedup vs baseline: 1.1130x; 1.1130x over previous
#include <cuda_runtime.h>
#include <cuda_bf16.h>
#include <cstdint>

// ---------------------------------------------------------------------------
// GaussianNNHeightmapEncoder
//   x: [B, 4096] -> reshape [B, 64, 64]
//   4x: h = lrelu( K_l @ (h @ W_l^T + b_l) )   (K_l row-stochastic => bias commutes)
//   flatten -> lrelu(h @ wm0^T + bm0) -> lrelu(@ wm1^T + bm1) -> [B, 60]
//
// R5: tcgen05 unavailable (ptxas target sm_103, not sm_103a). Compress GEMM
// uses mma.sync bf16 (HMMA) with 3-term hi/lo split for fp32-level accuracy,
// cp.async double-buffered staging, ldmatrix fragment loads.
// ---------------------------------------------------------------------------

#define MAXB 16384

__device__ float g_K[4 * 64 * 64];
__device__ __nv_bfloat16 g_hi[(size_t)MAXB * 4096];
__device__ __nv_bfloat16 g_lo[(size_t)MAXB * 4096];
__device__ __nv_bfloat16 g_w0hi[80 * 4096];
__device__ __nv_bfloat16 g_w0lo[80 * 4096];

__device__ __forceinline__ float lrelu(float v) { return fmaxf(v, 0.01f * v); }

__device__ __forceinline__ uint32_t smem_u32(const void* p) {
    uint32_t a;
    asm("{ .reg .u64 t; cvta.to.shared.u64 t, %1; cvt.u32.u64 %0, t; }" : "=r"(a) : "l"(p));
    return a;
}

__device__ __forceinline__ void split_bf16(float v, __nv_bfloat16& h, __nv_bfloat16& l) {
    h = __float2bfloat16(v);
    l = __float2bfloat16(v - __bfloat162float(h));
}

// ---- sm_80-level async copy / ldmatrix / mma helpers (compile on sm_103) ----
__device__ __forceinline__ void cp16(uint32_t dst, const void* src, int sz) {
    asm volatile("cp.async.cg.shared.global [%0], [%1], 16, %2;"
                 :: "r"(dst), "l"(src), "r"(sz) : "memory");
}
__device__ __forceinline__ void cp_commit() {
    asm volatile("cp.async.commit_group;" ::: "memory");
}
template <int N>
__device__ __forceinline__ void cp_wait() {
    asm volatile("cp.async.wait_group %0;" :: "n"(N) : "memory");
}
__device__ __forceinline__ void ldsm4(uint32_t* r, uint32_t addr) {
    asm volatile("ldmatrix.sync.aligned.m8n8.x4.shared.b16 {%0,%1,%2,%3}, [%4];"
                 : "=r"(r[0]), "=r"(r[1]), "=r"(r[2]), "=r"(r[3]) : "r"(addr));
}
__device__ __forceinline__ void ldsm2(uint32_t* r, uint32_t addr) {
    asm volatile("ldmatrix.sync.aligned.m8n8.x2.shared.b16 {%0,%1}, [%2];"
                 : "=r"(r[0]), "=r"(r[1]) : "r"(addr));
}
__device__ __forceinline__ void mma16816(float* d, const uint32_t* a, const uint32_t* b) {
    asm volatile(
        "mma.sync.aligned.m16n8k16.row.col.f32.bf16.bf16.f32 "
        "{%0,%1,%2,%3}, {%4,%5,%6,%7}, {%8,%9}, {%0,%1,%2,%3};"
        : "+f"(d[0]), "+f"(d[1]), "+f"(d[2]), "+f"(d[3])
        : "r"(a[0]), "r"(a[1]), "r"(a[2]), "r"(a[3]), "r"(b[0]), "r"(b[1]));
}

// ---------------------------------------------------------------------------
// Kernel P: normalized Gaussian kernels (4 x 64 x 64), fast __expf
// ---------------------------------------------------------------------------
__global__ void kprep_kernel(const float* __restrict__ s0, const float* __restrict__ s1,
                             const float* __restrict__ s2, const float* __restrict__ s3) {
    int tid = threadIdx.x;
    if (tid >= 256) return;
    int l = tid >> 6, i = tid & 63;
    float sig = (l == 0) ? s0[0] : (l == 1) ? s1[0] : (l == 2) ? s2[0] : s3[0];
    float inv = 1.0f / (2.0f * sig * sig);
    float e[64];
    float sum = 0.0f;
#pragma unroll 8
    for (int j = 0; j < 64; j++) {
        float d = (float)(i - j);
        e[j] = __expf(-d * d * inv);
        sum += e[j];
    }
    float r = 1.0f / fmaxf(sum, 1e-12f);
    float* dst = g_K + (l * 64 + i) * 64;
#pragma unroll 8
    for (int j = 0; j < 64; j++) dst[j] = e[j] * r;
}

// ---------------------------------------------------------------------------
// Kernel W: split wm0 (80x4096 fp32) into bf16 hi/lo
// ---------------------------------------------------------------------------
__global__ void wprep_kernel(const float* __restrict__ wm0) {
    int idx = blockIdx.x * 512 + threadIdx.x;      // 81920 float4s
    if (idx >= 81920) return;
    float4 v = *(const float4*)(wm0 + (size_t)idx * 4);
    __nv_bfloat16 h[4], l[4];
    split_bf16(v.x, h[0], l[0]);
    split_bf16(v.y, h[1], l[1]);
    split_bf16(v.z, h[2], l[2]);
    split_bf16(v.w, h[3], l[3]);
    *(uint2*)(g_w0hi + (size_t)idx * 4) = *(uint2*)h;
    *(uint2*)(g_w0lo + (size_t)idx * 4) = *(uint2*)l;
}

// ---------------------------------------------------------------------------
// Kernel B: fused 4 Gaussian layers (unchanged math; writes split bf16)
// ---------------------------------------------------------------------------
#define OFF_KR   0
#define OFF_W0   5120
#define OFF_W1   5632
#define OFF_W2   5760
#define OFF_W3   6272
#define OFF_B0   8320
#define OFF_B1   8328
#define OFF_B2   8344
#define OFF_B3   8376
#define OFF_SA   8448
#define GAUSS_SMEM_FLOATS (OFF_SA + 8 * 4096)

__device__ __forceinline__ void stage_k(float* __restrict__ KR, int l, int tid) {
    const float* __restrict__ src = g_K + l * 4096;
#pragma unroll
    for (int t = 0; t < 8; t++) {
        int idx = tid + t * 512;
        KR[(idx >> 6) * 80 + (idx & 63)] = src[idx];
    }
}

template <int CIN, bool LRELU>
__device__ __forceinline__ void kmul(const float* __restrict__ KR, const float* __restrict__ src,
                                     float* __restrict__ dst, int i) {
    constexpr int CC = (CIN < 16) ? CIN : 16;
#pragma unroll
    for (int c0 = 0; c0 < CIN; c0 += CC) {
        float acc[CC];
#pragma unroll
        for (int c = 0; c < CC; c++) acc[c] = 0.0f;
#pragma unroll 4
        for (int j4 = 0; j4 < 64; j4 += 4) {
            float4 kv = *(const float4*)&KR[i * 80 + j4];
#pragma unroll
            for (int c = 0; c < CC; c++) {
                float4 av = *(const float4*)&src[(c0 + c) * 64 + j4];
                acc[c] = fmaf(kv.x, av.x, fmaf(kv.y, av.y, fmaf(kv.z, av.z, fmaf(kv.w, av.w, acc[c]))));
            }
        }
#pragma unroll
        for (int c = 0; c < CC; c++) {
            float v = acc[c];
            if (LRELU) v = lrelu(v);
            dst[(c0 + c) * 64 + i] = v;
        }
    }
}

template <int CIN, int COUT>
__device__ __forceinline__ void wmul(const float* __restrict__ Ws, const float* __restrict__ bs,
                                     const float* __restrict__ src, float* __restrict__ dst, int i) {
    constexpr int OC = (COUT < 16) ? COUT : 16;
#pragma unroll
    for (int o0 = 0; o0 < COUT; o0 += OC) {
        float acc[OC];
#pragma unroll
        for (int o = 0; o < OC; o++) acc[o] = bs[o0 + o];
#pragma unroll 2
        for (int c4 = 0; c4 < CIN; c4 += 4) {
            float z0 = src[(c4 + 0) * 64 + i];
            float z1 = src[(c4 + 1) * 64 + i];
            float z2 = src[(c4 + 2) * 64 + i];
            float z3 = src[(c4 + 3) * 64 + i];
#pragma unroll
            for (int o = 0; o < OC; o++) {
                float4 wv = *(const float4*)&Ws[(o0 + o) * CIN + c4];
                acc[o] = fmaf(z0, wv.x, fmaf(z1, wv.y, fmaf(z2, wv.z, fmaf(z3, wv.w, acc[o]))));
            }
        }
#pragma unroll
        for (int o = 0; o < OC; o++) dst[(o0 + o) * 64 + i] = lrelu(acc[o]);
    }
}

template <int CIN, int COUT>
__device__ __forceinline__ void wmul_gmem_bf16(const float* __restrict__ Ws, const float* __restrict__ bs,
                                               const float* __restrict__ src,
                                               __nv_bfloat16* __restrict__ ghi,
                                               __nv_bfloat16* __restrict__ glo,
                                               int i, bool active) {
#pragma unroll
    for (int o0 = 0; o0 < COUT; o0 += 16) {
        float acc[16];
#pragma unroll
        for (int o = 0; o < 16; o++) acc[o] = bs[o0 + o];
#pragma unroll 2
        for (int c4 = 0; c4 < CIN; c4 += 4) {
            float z0 = src[(c4 + 0) * 64 + i];
            float z1 = src[(c4 + 1) * 64 + i];
            float z2 = src[(c4 + 2) * 64 + i];
            float z3 = src[(c4 + 3) * 64 + i];
#pragma unroll
            for (int o = 0; o < 16; o++) {
                float4 wv = *(const float4*)&Ws[(o0 + o) * CIN + c4];
                acc[o] = fmaf(z0, wv.x, fmaf(z1, wv.y, fmaf(z2, wv.z, fmaf(z3, wv.w, acc[o]))));
            }
        }
        if (active) {
#pragma unroll
            for (int q = 0; q < 4; q++) {
                __nv_bfloat16 hh[4], ll[4];
#pragma unroll
                for (int e = 0; e < 4; e++) {
                    float v = lrelu(acc[q * 4 + e]);
                    split_bf16(v, hh[e], ll[e]);
                }
                *(uint2*)(ghi + o0 + q * 4) = *(uint2*)hh;
                *(uint2*)(glo + o0 + q * 4) = *(uint2*)ll;
            }
        }
    }
}

__global__ __launch_bounds__(512, 1) void gauss_kernel(
    const float* __restrict__ x,
    const float* __restrict__ w0, const float* __restrict__ b0,
    const float* __restrict__ w1, const float* __restrict__ b1,
    const float* __restrict__ w2, const float* __restrict__ b2,
    const float* __restrict__ w3, const float* __restrict__ b3,
    int B) {
    extern __shared__ float sm[];
    float* KR  = sm + OFF_KR;
    float* W0s = sm + OFF_W0;
    float* W1s = sm + OFF_W1;
    float* W2s = sm + OFF_W2;
    float* W3s = sm + OFF_W3;
    float* b0s = sm + OFF_B0;
    float* b1s = sm + OFF_B1;
    float* b2s = sm + OFF_B2;
    float* b3s = sm + OFF_B3;

    int tid = threadIdx.x;

    for (int t = tid; t < 512;  t += 512) W0s[t] = w0[t];
    for (int t = tid; t < 128;  t += 512) W1s[t] = w1[t];
    for (int t = tid; t < 512;  t += 512) W2s[t] = w2[t];
    for (int t = tid; t < 2048; t += 512) W3s[t] = w3[t];
    if (tid < 8)  b0s[tid] = b0[tid];
    if (tid < 16) b1s[tid] = b1[tid];
    if (tid < 32) b2s[tid] = b2[tid];
    if (tid < 64) b3s[tid] = b3[tid];
    stage_k(KR, 0, tid);
    __syncthreads();

    int s = tid >> 6, i = tid & 63;
    long b = (long)blockIdx.x * 8 + s;
    bool active = (b < B);
    float* A  = sm + OFF_SA + s * 4096;
    float* Bb = A + 2048;

    // L0: XP = X @ W0^T + b0 ; A = lrelu(K0 @ XP)
    {
        const float* xrow = x + (active ? b * 4096 + (long)i * 64 : 0);
        float acc[8];
#pragma unroll
        for (int o = 0; o < 8; o++) acc[o] = b0s[o];
#pragma unroll
        for (int half = 0; half < 2; half++) {
            float4 xr[8];
#pragma unroll
            for (int q = 0; q < 8; q++) {
                xr[q] = active ? *(const float4*)&xrow[half * 32 + q * 4]
                               : make_float4(0.f, 0.f, 0.f, 0.f);
            }
#pragma unroll
            for (int o = 0; o < 8; o++) {
#pragma unroll
                for (int q = 0; q < 8; q++) {
                    float4 wv = *(const float4*)&W0s[o * 64 + half * 32 + q * 4];
                    acc[o] = fmaf(xr[q].x, wv.x, fmaf(xr[q].y, wv.y,
                             fmaf(xr[q].z, wv.z, fmaf(xr[q].w, wv.w, acc[o]))));
                }
            }
        }
#pragma unroll
        for (int o = 0; o < 8; o++) Bb[o * 64 + i] = acc[o];
    }
    __syncthreads();
    kmul<8, true>(KR, Bb, A, i);

    // L1
    __syncthreads();
    stage_k(KR, 1, tid);
    __syncthreads();
    kmul<8, false>(KR, A, Bb, i);
    wmul<8, 16>(W1s, b1s, Bb, A, i);

    // L2
    __syncthreads();
    stage_k(KR, 2, tid);
    __syncthreads();
    kmul<16, false>(KR, A, Bb, i);
    wmul<16, 32>(W2s, b2s, Bb, A, i);

    // L3 -> split bf16 to gmem
    __syncthreads();
    stage_k(KR, 3, tid);
    __syncthreads();
    kmul<32, false>(KR, A, Bb, i);
    size_t base = active ? ((size_t)b * 4096 + (size_t)i * 64) : 0;
    wmul_gmem_bf16<32, 64>(W3s, b3s, Bb, g_hi + base, g_lo + base, i, active);
}

// ---------------------------------------------------------------------------
// Kernel C (HMMA): D[128,80] = h @ wm0^T via 3-term bf16 split mma.sync,
// fused +bm0/lrelu and 80->60 second layer.
//   8 warps = 4(M) x 2(N); warp tile 32x40 = 2x5 m16n8k16 frags.
//   smem rows padded to 144B (bank-conflict-free cp.async + ldmatrix).
// ---------------------------------------------------------------------------
#define CP_SW1     0                        // wm1 fp32: 4800 floats = 19200 B
#define CP_STG0    19456                    // 256B-aligned stage base
#define CP_A_HI    0                        // 128 x 144B = 18432
#define CP_A_LO    18432
#define CP_B_HI    36864                    // 80 x 144B = 11520
#define CP_B_LO    48384
#define CP_STG_SZ  59904
#define CP_SMEM_BYTES (CP_STG0 + 2 * CP_STG_SZ)   // 139264

__global__ __launch_bounds__(512, 1) void compress_mma_kernel(
    const float* __restrict__ bm0, const float* __restrict__ wm1,
    const float* __restrict__ bm1, float* __restrict__ out, int B) {
    extern __shared__ char smem[];
    uint32_t sb = smem_u32(smem);
    int tid = threadIdx.x;
    long m0 = (long)blockIdx.x * 128;

    float* sW1 = (float*)(smem + CP_SW1);
    for (int t = tid; t < 4800; t += 512) sW1[t] = wm1[t];

    int lane = tid & 31, w = tid >> 5;
    int mw = w >> 1, nw = w & 1;

    auto load_chunk = [&](int c, int bsel) {
        uint32_t stg = sb + CP_STG0 + bsel * CP_STG_SZ;
        int k0 = c * 64;
        for (int q = tid; q < 1024; q += 512) {
            int m = q >> 3, kk = q & 7;
            long gm = m0 + m;
            int ok = (gm < B);
            size_t off = (size_t)(ok ? gm : 0) * 4096 + k0 + kk * 8;
            int sz = ok ? 16 : 0;
            uint32_t d = stg + m * 144 + kk * 16;
            cp16(d + CP_A_HI, g_hi + off, sz);
            cp16(d + CP_A_LO, g_lo + off, sz);
        }
        for (int q = tid; q < 640; q += 512) {
            int o = q >> 3, kk = q & 7;
            size_t off = (size_t)o * 4096 + k0 + kk * 8;
            uint32_t d = stg + o * 144 + kk * 16;
            cp16(d + CP_B_HI, g_w0hi + off, 16);
            cp16(d + CP_B_LO, g_w0lo + off, 16);
        }
        cp_commit();
    };

    float acc[2][5][4];
#pragma unroll
    for (int mt = 0; mt < 2; mt++)
#pragma unroll
        for (int nt = 0; nt < 5; nt++)
#pragma unroll
            for (int e = 0; e < 4; e++) acc[mt][nt][e] = 0.0f;

    load_chunk(0, 0);
    load_chunk(1, 1);

    // per-thread ldmatrix address components (byte offsets into the stage)
    uint32_t aoff0 = (uint32_t)(mw * 32 + ((lane >> 3) & 1) * 8 + (lane & 7)) * 144
                     + (uint32_t)(lane >> 4) * 16;
    int g = lane >> 3;
    uint32_t boff0 = (uint32_t)(nw * 40 + (g >> 1) * 8 + (lane & 7)) * 144 + (uint32_t)(g & 1) * 16;
    uint32_t boff2 = (uint32_t)(nw * 40 + 32 + (lane & 7)) * 144 + (uint32_t)((lane >> 3) & 1) * 16;

#pragma unroll 1
    for (int c = 0; c < 64; c++) {
        int bsel = c & 1;
        cp_wait<1>();
        __syncthreads();
        uint32_t stg = sb + CP_STG0 + bsel * CP_STG_SZ;

#pragma unroll
        for (int ks = 0; ks < 4; ks++) {
            uint32_t ahi[2][4], alo[2][4], bhi[5][2], blo[5][2];
            uint32_t ao = stg + aoff0 + ks * 32;
            ldsm4(ahi[0], ao + CP_A_HI);
            ldsm4(ahi[1], ao + CP_A_HI + 16 * 144);
            ldsm4(alo[0], ao + CP_A_LO);
            ldsm4(alo[1], ao + CP_A_LO + 16 * 144);
            uint32_t bo = stg + boff0 + ks * 32;
            uint32_t bo2 = stg + boff2 + ks * 32;
            ldsm4(&bhi[0][0], bo + CP_B_HI);
            ldsm4(&bhi[2][0], bo + CP_B_HI + 16 * 144);
            ldsm2(&bhi[4][0], bo2 + CP_B_HI);
            ldsm4(&blo[0][0], bo + CP_B_LO);
            ldsm4(&blo[2][0], bo + CP_B_LO + 16 * 144);
            ldsm2(&blo[4][0], bo2 + CP_B_LO);
#pragma unroll
            for (int mt = 0; mt < 2; mt++)
#pragma unroll
                for (int nt = 0; nt < 5; nt++) {
                    mma16816(acc[mt][nt], ahi[mt], bhi[nt]);
                    mma16816(acc[mt][nt], alo[mt], bhi[nt]);
                    mma16816(acc[mt][nt], ahi[mt], blo[nt]);
                }
        }
        __syncthreads();
        if (c + 2 < 64) load_chunk(c + 2, bsel);
        else cp_commit();                        // keep group count consistent
    }

    // Epilogue: acc -> +bm0 -> lrelu -> h1[128][81] (overlays stage area)
    float* h1 = (float*)(smem + CP_STG0);
    int qrow = lane >> 2;
    int qcol = (lane & 3) * 2;
#pragma unroll
    for (int mt = 0; mt < 2; mt++)
#pragma unroll
        for (int i = 0; i < 2; i++) {
            int r = mw * 32 + mt * 16 + qrow + i * 8;
#pragma unroll
            for (int nt = 0; nt < 5; nt++)
#pragma unroll
                for (int j = 0; j < 2; j++) {
                    int col = nw * 40 + nt * 8 + qcol + j;
                    h1[r * 81 + col] = lrelu(acc[mt][nt][i * 2 + j] + __ldg(&bm0[col]));
                }
        }
    __syncthreads();

    // Second layer: 128 rows x 60 outs = 7680 outputs over 512 threads.
#pragma unroll 1
    for (int ii = 0; ii < 15; ii++) {
        int idx = tid + ii * 512;
        int m = idx & 127, o2 = idx >> 7;
        float a = __ldg(&bm1[o2]);
#pragma unroll 4
        for (int c4 = 0; c4 < 80; c4 += 4) {
            float4 wv = *(const float4*)&sW1[o2 * 80 + c4];
            a = fmaf(h1[m * 81 + c4 + 0], wv.x,
                fmaf(h1[m * 81 + c4 + 1], wv.y,
                fmaf(h1[m * 81 + c4 + 2], wv.z,
                fmaf(h1[m * 81 + c4 + 3], wv.w, a))));
        }
        long gm = m0 + m;
        if (gm < B) out[gm * 60 + o2] = lrelu(a);
    }
}

// ---------------------------------------------------------------------------
extern "C" void kernel_launch(void* const* d_in, const int* in_sizes, int n_in,
                              void* d_out, int out_size) {
    const float* x   = (const float*)d_in[0];
    const float* w0  = (const float*)d_in[1];
    const float* b0  = (const float*)d_in[2];
    const float* s0  = (const float*)d_in[3];
    const float* w1  = (const float*)d_in[4];
    const float* b1  = (const float*)d_in[5];
    const float* s1  = (const float*)d_in[6];
    const float* w2  = (const float*)d_in[7];
    const float* b2  = (const float*)d_in[8];
    const float* s2  = (const float*)d_in[9];
    const float* w3  = (const float*)d_in[10];
    const float* b3  = (const float*)d_in[11];
    const float* s3  = (const float*)d_in[12];
    const float* wm0 = (const float*)d_in[13];
    const float* bm0 = (const float*)d_in[14];
    const float* wm1 = (const float*)d_in[15];
    const float* bm1 = (const float*)d_in[16];

    int B = in_sizes[0] / 4096;
    if (B > MAXB) B = MAXB;

    cudaFuncSetAttribute((const void*)gauss_kernel,
                         cudaFuncAttributeMaxDynamicSharedMemorySize,
                         GAUSS_SMEM_FLOATS * 4);
    cudaFuncSetAttribute((const void*)compress_mma_kernel,
                         cudaFuncAttributeMaxDynamicSharedMemorySize,
                         CP_SMEM_BYTES);

    kprep_kernel<<<1, 256>>>(s0, s1, s2, s3);
    wprep_kernel<<<160, 512>>>(wm0);
    gauss_kernel<<<(B + 7) / 8, 512, GAUSS_SMEM_FLOATS * 4>>>(
        x, w0, b0, w1, b1, w2, b2, w3, b3, B);
    compress_mma_kernel<<<(B + 127) / 128, 512, CP_SMEM_BYTES>>>(
        bm0, wm1, bm1, (float*)d_out, B);
}

// round 12
// speedup vs baseline: 1.8131x; 1.6290x over previous
#include <cuda_runtime.h>
#include <cuda_bf16.h>
#include <cstdint>

// ---------------------------------------------------------------------------
// GaussianNNHeightmapEncoder — R9
//   gauss stage ported to HMMA (mma.sync bf16, 3-term hi/lo split):
//     K-mul:  [64x64] @ [64 x 8C]  (samples batched along N, channel-major state)
//     W-mul:  [512 x Cin] @ [Cin x Cout] (samples batched along M, row-major state)
//   compress stage unchanged (HMMA, 207 us).
// ---------------------------------------------------------------------------

#define MAXB 16384

__device__ float g_K[4 * 64 * 64];
__device__ __nv_bfloat16 g_hi[(size_t)MAXB * 4096];
__device__ __nv_bfloat16 g_lo[(size_t)MAXB * 4096];
__device__ __nv_bfloat16 g_w0hi[80 * 4096];
__device__ __nv_bfloat16 g_w0lo[80 * 4096];

__device__ __forceinline__ float lrelu(float v) { return fmaxf(v, 0.01f * v); }

__device__ __forceinline__ uint32_t smem_u32(const void* p) {
    uint32_t a;
    asm("{ .reg .u64 t; cvta.to.shared.u64 t, %1; cvt.u32.u64 %0, t; }" : "=r"(a) : "l"(p));
    return a;
}

__device__ __forceinline__ void split_bf16(float v, __nv_bfloat16& h, __nv_bfloat16& l) {
    h = __float2bfloat16(v);
    l = __float2bfloat16(v - __bfloat162float(h));
}
__device__ __forceinline__ void split2(float v0, float v1, uint32_t& hi, uint32_t& lo) {
    __nv_bfloat16 h0, l0, h1, l1;
    split_bf16(v0, h0, l0);
    split_bf16(v1, h1, l1);
    __nv_bfloat162 H, L;
    H.x = h0; H.y = h1;
    L.x = l0; L.y = l1;
    hi = *(uint32_t*)&H;
    lo = *(uint32_t*)&L;
}

// ---- async copy / ldmatrix / mma helpers ----
__device__ __forceinline__ void cp16(uint32_t dst, const void* src, int sz) {
    asm volatile("cp.async.cg.shared.global [%0], [%1], 16, %2;"
                 :: "r"(dst), "l"(src), "r"(sz) : "memory");
}
__device__ __forceinline__ void cp_commit() {
    asm volatile("cp.async.commit_group;" ::: "memory");
}
template <int N>
__device__ __forceinline__ void cp_wait() {
    asm volatile("cp.async.wait_group %0;" :: "n"(N) : "memory");
}
__device__ __forceinline__ void ldsm4(uint32_t* r, uint32_t addr) {
    asm volatile("ldmatrix.sync.aligned.m8n8.x4.shared.b16 {%0,%1,%2,%3}, [%4];"
                 : "=r"(r[0]), "=r"(r[1]), "=r"(r[2]), "=r"(r[3]) : "r"(addr));
}
__device__ __forceinline__ void ldsm2(uint32_t* r, uint32_t addr) {
    asm volatile("ldmatrix.sync.aligned.m8n8.x2.shared.b16 {%0,%1}, [%2];"
                 : "=r"(r[0]), "=r"(r[1]) : "r"(addr));
}
__device__ __forceinline__ void mma16816(float* d, const uint32_t* a, const uint32_t* b) {
    asm volatile(
        "mma.sync.aligned.m16n8k16.row.col.f32.bf16.bf16.f32 "
        "{%0,%1,%2,%3}, {%4,%5,%6,%7}, {%8,%9}, {%0,%1,%2,%3};"
        : "+f"(d[0]), "+f"(d[1]), "+f"(d[2]), "+f"(d[3])
        : "r"(a[0]), "r"(a[1]), "r"(a[2]), "r"(a[3]), "r"(b[0]), "r"(b[1]));
}

// ---------------------------------------------------------------------------
// Kernel P: normalized Gaussian kernels (4 x 64 x 64)
// ---------------------------------------------------------------------------
__global__ void kprep_kernel(const float* __restrict__ s0, const float* __restrict__ s1,
                             const float* __restrict__ s2, const float* __restrict__ s3) {
    int tid = threadIdx.x;
    if (tid >= 256) return;
    int l = tid >> 6, i = tid & 63;
    float sig = (l == 0) ? s0[0] : (l == 1) ? s1[0] : (l == 2) ? s2[0] : s3[0];
    float inv = 1.0f / (2.0f * sig * sig);
    float e[64];
    float sum = 0.0f;
#pragma unroll 8
    for (int j = 0; j < 64; j++) {
        float d = (float)(i - j);
        e[j] = __expf(-d * d * inv);
        sum += e[j];
    }
    float r = 1.0f / fmaxf(sum, 1e-12f);
    float* dst = g_K + (l * 64 + i) * 64;
#pragma unroll 8
    for (int j = 0; j < 64; j++) dst[j] = e[j] * r;
}

// ---------------------------------------------------------------------------
// Kernel W: split wm0 (80x4096 fp32) into bf16 hi/lo
// ---------------------------------------------------------------------------
__global__ void wprep_kernel(const float* __restrict__ wm0) {
    int idx = blockIdx.x * 512 + threadIdx.x;
    if (idx >= 81920) return;
    float4 v = *(const float4*)(wm0 + (size_t)idx * 4);
    __nv_bfloat16 h[4], l[4];
    split_bf16(v.x, h[0], l[0]);
    split_bf16(v.y, h[1], l[1]);
    split_bf16(v.z, h[2], l[2]);
    split_bf16(v.w, h[3], l[3]);
    *(uint2*)(g_w0hi + (size_t)idx * 4) = *(uint2*)h;
    *(uint2*)(g_w0lo + (size_t)idx * 4) = *(uint2*)l;
}

// ---------------------------------------------------------------------------
// gauss_mma smem layout (bytes)
//   KA:  K matrix hi/lo, row-major [64][72] bf16 (144 B rows)
//   W:   W1(rows 0-15) W2(16-47) W3(48-111), [.][40] bf16 (80 B rows), k-padded
//   RM:  state row-major [512][40] bf16   (row = s*64+i, col = c)
//   CM:  state chan-major [256][72] bf16  (row = s*C+c,  col = j)
// ---------------------------------------------------------------------------
#define GM_W0F   0
#define GM_B0F   2048
#define GM_B1F   2080
#define GM_B2F   2144
#define GM_B3F   2272
#define GM_KA_HI 2560
#define GM_KA_LO 11776
#define GM_W_HI  20992
#define GM_W_LO  29952
#define GM_RM_HI 38912
#define GM_RM_LO 79872
#define GM_CM_HI 120832
#define GM_CM_LO 157696
#define GM_SMEM  194560

__device__ __forceinline__ void stage_Kl(char* smem, int l, int tid) {
    const float* __restrict__ src = g_K + l * 4096;
    for (int t = tid; t < 4096; t += 512) {
        int i = t >> 6, j = t & 63;
        __nv_bfloat16 h, lo;
        split_bf16(src[t], h, lo);
        *(__nv_bfloat16*)(smem + GM_KA_HI + ((i * 72 + j) << 1)) = h;
        *(__nv_bfloat16*)(smem + GM_KA_LO + ((i * 72 + j) << 1)) = lo;
    }
}

// K-mul: D[64 x 8C] = K @ CM^T ; epilogue -> CM (lrelu, L0) or RM (pre-act)
template <int C, bool TO_CM>
__device__ __forceinline__ void kmul_mma(char* smem, uint32_t sb, int lane, int w) {
    constexpr int CH = C / 4;                       // n8-tiles per warp
    constexpr int SH = (C == 8) ? 3 : (C == 16) ? 4 : 5;
    int mt = w & 3;
    int n0t = (w >> 2) * CH;
    int g = lane >> 3;
    float acc[CH][4];
#pragma unroll
    for (int t = 0; t < CH; t++)
#pragma unroll
        for (int e = 0; e < 4; e++) acc[t][e] = 0.0f;

    uint32_t arow0 = (uint32_t)(mt * 16 + (lane & 15)) * 144 + (uint32_t)(lane >> 4) * 16;
#pragma unroll
    for (int ks = 0; ks < 4; ks++) {
        uint32_t ahi[4], alo[4];
        uint32_t ao = arow0 + ks * 32;
        ldsm4(ahi, sb + GM_KA_HI + ao);
        ldsm4(alo, sb + GM_KA_LO + ao);
#pragma unroll
        for (int p = 0; p < CH / 2; p++) {
            uint32_t brow = (uint32_t)((n0t + p * 2) * 8 + (g >> 1) * 8 + (lane & 7)) * 144
                          + (uint32_t)(g & 1) * 16 + ks * 32;
            uint32_t bhi[4], blo[4];
            ldsm4(bhi, sb + GM_CM_HI + brow);
            ldsm4(blo, sb + GM_CM_LO + brow);
            mma16816(acc[p * 2],     ahi, bhi);
            mma16816(acc[p * 2 + 1], ahi, bhi + 2);
            mma16816(acc[p * 2],     alo, bhi);
            mma16816(acc[p * 2 + 1], alo, bhi + 2);
            mma16816(acc[p * 2],     ahi, blo);
            mma16816(acc[p * 2 + 1], ahi, blo + 2);
        }
    }
    if (TO_CM) __syncthreads();                     // in-place CM: all reads done first
    int r0 = mt * 16 + (lane >> 2);
    int cp = (lane & 3) * 2;
#pragma unroll
    for (int t = 0; t < CH; t++) {
        int nn = (n0t + t) * 8 + cp;
#pragma unroll
        for (int h2 = 0; h2 < 2; h2++) {
            int i = r0 + h2 * 8;
            float v0 = acc[t][h2 * 2 + 0], v1 = acc[t][h2 * 2 + 1];
            if (TO_CM) {
                v0 = lrelu(v0); v1 = lrelu(v1);
                __nv_bfloat16 h0, l0, h1, l1;
                split_bf16(v0, h0, l0);
                split_bf16(v1, h1, l1);
                *(__nv_bfloat16*)(smem + GM_CM_HI + (((nn    ) * 72 + i) << 1)) = h0;
                *(__nv_bfloat16*)(smem + GM_CM_HI + (((nn + 1) * 72 + i) << 1)) = h1;
                *(__nv_bfloat16*)(smem + GM_CM_LO + (((nn    ) * 72 + i) << 1)) = l0;
                *(__nv_bfloat16*)(smem + GM_CM_LO + (((nn + 1) * 72 + i) << 1)) = l1;
            } else {
                int s = nn >> SH, c = nn & (C - 1);
                uint32_t off = (((uint32_t)(s * 64 + i) * 40 + c) << 1);
                uint32_t hi, lo;
                split2(v0, v1, hi, lo);
                *(uint32_t*)(smem + GM_RM_HI + off) = hi;
                *(uint32_t*)(smem + GM_RM_LO + off) = lo;
            }
        }
    }
}

// W-mul: D[512 x Cout] = RM @ W^T (+bias, lrelu); -> CM (L1,2) or gmem (L3)
template <int CIN, int COUT, int L>
__device__ __forceinline__ void wmul_mma(char* smem, uint32_t sb, int lane, int w,
                                         const float* __restrict__ bias,
                                         long bbase, int Bn) {
    constexpr int KS = (CIN + 15) / 16;
    constexpr int NT = COUT / 8;
    constexpr int NC = (NT < 4) ? NT : 4;
    constexpr int NCH = NT / NC;
    constexpr int WROW = (L == 1) ? 0 : (L == 2) ? 16 : 48;
    int mt0 = w * 2;
    int g = lane >> 3;
    int r0 = (lane >> 2);
    int cp = (lane & 3) * 2;
#pragma unroll
    for (int ch = 0; ch < NCH; ch++) {
        float acc[2][NC][4];
#pragma unroll
        for (int m = 0; m < 2; m++)
#pragma unroll
            for (int t = 0; t < NC; t++)
#pragma unroll
                for (int e = 0; e < 4; e++) acc[m][t][e] = 0.0f;
#pragma unroll
        for (int ks = 0; ks < KS; ks++) {
            uint32_t ahi[2][4], alo[2][4];
#pragma unroll
            for (int m = 0; m < 2; m++) {
                uint32_t ao = (uint32_t)((mt0 + m) * 16 + (lane & 15)) * 80
                            + (uint32_t)(lane >> 4) * 16 + ks * 32;
                ldsm4(ahi[m], sb + GM_RM_HI + ao);
                ldsm4(alo[m], sb + GM_RM_LO + ao);
            }
#pragma unroll
            for (int p = 0; p < NC / 2; p++) {
                uint32_t brow = (uint32_t)(WROW + (ch * NC + p * 2) * 8 + (g >> 1) * 8 + (lane & 7)) * 80
                              + (uint32_t)(g & 1) * 16 + ks * 32;
                uint32_t bhi[4], blo[4];
                ldsm4(bhi, sb + GM_W_HI + brow);
                ldsm4(blo, sb + GM_W_LO + brow);
#pragma unroll
                for (int m = 0; m < 2; m++) {
                    mma16816(acc[m][p * 2],     ahi[m], bhi);
                    mma16816(acc[m][p * 2 + 1], ahi[m], bhi + 2);
                    mma16816(acc[m][p * 2],     alo[m], bhi);
                    mma16816(acc[m][p * 2 + 1], alo[m], bhi + 2);
                    mma16816(acc[m][p * 2],     ahi[m], blo);
                    mma16816(acc[m][p * 2 + 1], ahi[m], blo + 2);
                }
            }
        }
#pragma unroll
        for (int m = 0; m < 2; m++) {
#pragma unroll
            for (int t = 0; t < NC; t++) {
                int o = (ch * NC + t) * 8 + cp;
                float b0v = bias[o], b1v = bias[o + 1];
#pragma unroll
                for (int h2 = 0; h2 < 2; h2++) {
                    int mg = (mt0 + m) * 16 + r0 + h2 * 8;
                    int s = mg >> 6, i = mg & 63;
                    float v0 = lrelu(acc[m][t][h2 * 2 + 0] + b0v);
                    float v1 = lrelu(acc[m][t][h2 * 2 + 1] + b1v);
                    if (L < 3) {
                        int row = s * COUT + o;
                        __nv_bfloat16 h0, l0, h1, l1;
                        split_bf16(v0, h0, l0);
                        split_bf16(v1, h1, l1);
                        *(__nv_bfloat16*)(smem + GM_CM_HI + (((row    ) * 72 + i) << 1)) = h0;
                        *(__nv_bfloat16*)(smem + GM_CM_HI + (((row + 1) * 72 + i) << 1)) = h1;
                        *(__nv_bfloat16*)(smem + GM_CM_LO + (((row    ) * 72 + i) << 1)) = l0;
                        *(__nv_bfloat16*)(smem + GM_CM_LO + (((row + 1) * 72 + i) << 1)) = l1;
                    } else {
                        long bb = bbase + s;
                        if (bb < Bn) {
                            uint32_t hi, lo;
                            split2(v0, v1, hi, lo);
                            size_t word = ((size_t)bb * 4096 + (size_t)i * 64 + o) >> 1;
                            ((uint32_t*)g_hi)[word] = hi;
                            ((uint32_t*)g_lo)[word] = lo;
                        }
                    }
                }
            }
        }
    }
}

__global__ __launch_bounds__(512, 1) void gauss_mma_kernel(
    const float* __restrict__ x,
    const float* __restrict__ w0, const float* __restrict__ b0,
    const float* __restrict__ w1, const float* __restrict__ b1,
    const float* __restrict__ w2, const float* __restrict__ b2,
    const float* __restrict__ w3, const float* __restrict__ b3,
    int B) {
    extern __shared__ char smem[];
    uint32_t sb = smem_u32(smem);
    int tid = threadIdx.x, lane = tid & 31, w = tid >> 5;

    // zero W region (k-padding) and RM (c-padding for L1's k16 step)
    for (int t = tid; t < 4480; t += 512) ((uint32_t*)(smem + GM_W_HI))[t] = 0u;
    for (int t = tid; t < 20480; t += 512) ((uint32_t*)(smem + GM_RM_HI))[t] = 0u;
    __syncthreads();

    // stage constants
    float* W0s = (float*)(smem + GM_W0F);
    for (int t = tid; t < 512; t += 512) W0s[t] = w0[t];
    if (tid < 8)  ((float*)(smem + GM_B0F))[tid] = b0[tid];
    if (tid < 16) ((float*)(smem + GM_B1F))[tid] = b1[tid];
    if (tid < 32) ((float*)(smem + GM_B2F))[tid] = b2[tid];
    if (tid < 64) ((float*)(smem + GM_B3F))[tid] = b3[tid];
    for (int t = tid; t < 128; t += 512) {          // W1 [16][8] -> rows 0..15
        int o = t >> 3, c = t & 7;
        __nv_bfloat16 h, l;
        split_bf16(w1[t], h, l);
        *(__nv_bfloat16*)(smem + GM_W_HI + ((o * 40 + c) << 1)) = h;
        *(__nv_bfloat16*)(smem + GM_W_LO + ((o * 40 + c) << 1)) = l;
    }
    for (int t = tid; t < 512; t += 512) {          // W2 [32][16] -> rows 16..47
        int o = t >> 4, c = t & 15;
        __nv_bfloat16 h, l;
        split_bf16(w2[t], h, l);
        *(__nv_bfloat16*)(smem + GM_W_HI + (((16 + o) * 40 + c) << 1)) = h;
        *(__nv_bfloat16*)(smem + GM_W_LO + (((16 + o) * 40 + c) << 1)) = l;
    }
    for (int t = tid; t < 2048; t += 512) {         // W3 [64][32] -> rows 48..111
        int o = t >> 5, c = t & 31;
        __nv_bfloat16 h, l;
        split_bf16(w3[t], h, l);
        *(__nv_bfloat16*)(smem + GM_W_HI + (((48 + o) * 40 + c) << 1)) = h;
        *(__nv_bfloat16*)(smem + GM_W_LO + (((48 + o) * 40 + c) << 1)) = l;
    }
    stage_Kl(smem, 0, tid);
    __syncthreads();

    // ---- L0 (FFMA): XP = X @ W0^T + b0 -> CM[(s*8+o)][i]
    {
        int s = tid >> 6, i = tid & 63;
        long b = (long)blockIdx.x * 8 + s;
        bool act = (b < B);
        const float* xrow = x + (act ? b * 4096 + (long)i * 64 : 0);
        const float* b0s = (const float*)(smem + GM_B0F);
        float acc[8];
#pragma unroll
        for (int o = 0; o < 8; o++) acc[o] = b0s[o];
#pragma unroll
        for (int half = 0; half < 2; half++) {
            float4 xr[8];
#pragma unroll
            for (int q = 0; q < 8; q++)
                xr[q] = act ? *(const float4*)&xrow[half * 32 + q * 4]
                            : make_float4(0.f, 0.f, 0.f, 0.f);
#pragma unroll
            for (int o = 0; o < 8; o++) {
#pragma unroll
                for (int q = 0; q < 8; q++) {
                    float4 wv = *(const float4*)&W0s[o * 64 + half * 32 + q * 4];
                    acc[o] = fmaf(xr[q].x, wv.x, fmaf(xr[q].y, wv.y,
                             fmaf(xr[q].z, wv.z, fmaf(xr[q].w, wv.w, acc[o]))));
                }
            }
        }
#pragma unroll
        for (int o = 0; o < 8; o++) {
            __nv_bfloat16 h, l;
            split_bf16(acc[o], h, l);
            *(__nv_bfloat16*)(smem + GM_CM_HI + (((s * 8 + o) * 72 + i) << 1)) = h;
            *(__nv_bfloat16*)(smem + GM_CM_LO + (((s * 8 + o) * 72 + i) << 1)) = l;
        }
    }
    __syncthreads();

    const float* b1s = (const float*)(smem + GM_B1F);
    const float* b2s = (const float*)(smem + GM_B2F);
    const float* b3s = (const float*)(smem + GM_B3F);
    long bbase = (long)blockIdx.x * 8;

    kmul_mma<8, true>(smem, sb, lane, w);           // K0 @ XP, lrelu -> CM (in-place)
    stage_Kl(smem, 1, tid);
    __syncthreads();

    kmul_mma<8, false>(smem, sb, lane, w);          // K1 @ h -> RM
    __syncthreads();
    wmul_mma<8, 16, 1>(smem, sb, lane, w, b1s, bbase, B);   // -> CM
    stage_Kl(smem, 2, tid);
    __syncthreads();

    kmul_mma<16, false>(smem, sb, lane, w);         // K2 @ h -> RM
    __syncthreads();
    wmul_mma<16, 32, 2>(smem, sb, lane, w, b2s, bbase, B);  // -> CM
    stage_Kl(smem, 3, tid);
    __syncthreads();

    kmul_mma<32, false>(smem, sb, lane, w);         // K3 @ h -> RM
    __syncthreads();
    wmul_mma<32, 64, 3>(smem, sb, lane, w, b3s, bbase, B);  // -> g_hi/g_lo
}

// ---------------------------------------------------------------------------
// Kernel C (HMMA): unchanged from R8 (207 us)
// ---------------------------------------------------------------------------
#define CP_SW1     0
#define CP_STG0    19456
#define CP_A_HI    0
#define CP_A_LO    18432
#define CP_B_HI    36864
#define CP_B_LO    48384
#define CP_STG_SZ  59904
#define CP_SMEM_BYTES (CP_STG0 + 2 * CP_STG_SZ)

__global__ __launch_bounds__(512, 1) void compress_mma_kernel(
    const float* __restrict__ bm0, const float* __restrict__ wm1,
    const float* __restrict__ bm1, float* __restrict__ out, int B) {
    extern __shared__ char smem[];
    uint32_t sb = smem_u32(smem);
    int tid = threadIdx.x;
    long m0 = (long)blockIdx.x * 128;

    float* sW1 = (float*)(smem + CP_SW1);
    for (int t = tid; t < 4800; t += 512) sW1[t] = wm1[t];

    int lane = tid & 31, w = tid >> 5;
    int mw = w >> 1, nw = w & 1;

    auto load_chunk = [&](int c, int bsel) {
        uint32_t stg = sb + CP_STG0 + bsel * CP_STG_SZ;
        int k0 = c * 64;
        for (int q = tid; q < 1024; q += 512) {
            int m = q >> 3, kk = q & 7;
            long gm = m0 + m;
            int ok = (gm < B);
            size_t off = (size_t)(ok ? gm : 0) * 4096 + k0 + kk * 8;
            int sz = ok ? 16 : 0;
            uint32_t d = stg + m * 144 + kk * 16;
            cp16(d + CP_A_HI, g_hi + off, sz);
            cp16(d + CP_A_LO, g_lo + off, sz);
        }
        for (int q = tid; q < 640; q += 512) {
            int o = q >> 3, kk = q & 7;
            size_t off = (size_t)o * 4096 + k0 + kk * 8;
            uint32_t d = stg + o * 144 + kk * 16;
            cp16(d + CP_B_HI, g_w0hi + off, 16);
            cp16(d + CP_B_LO, g_w0lo + off, 16);
        }
        cp_commit();
    };

    float acc[2][5][4];
#pragma unroll
    for (int mt = 0; mt < 2; mt++)
#pragma unroll
        for (int nt = 0; nt < 5; nt++)
#pragma unroll
            for (int e = 0; e < 4; e++) acc[mt][nt][e] = 0.0f;

    load_chunk(0, 0);
    load_chunk(1, 1);

    uint32_t aoff0 = (uint32_t)(mw * 32 + ((lane >> 3) & 1) * 8 + (lane & 7)) * 144
                     + (uint32_t)(lane >> 4) * 16;
    int g = lane >> 3;
    uint32_t boff0 = (uint32_t)(nw * 40 + (g >> 1) * 8 + (lane & 7)) * 144 + (uint32_t)(g & 1) * 16;
    uint32_t boff2 = (uint32_t)(nw * 40 + 32 + (lane & 7)) * 144 + (uint32_t)((lane >> 3) & 1) * 16;

#pragma unroll 1
    for (int c = 0; c < 64; c++) {
        int bsel = c & 1;
        cp_wait<1>();
        __syncthreads();
        uint32_t stg = sb + CP_STG0 + bsel * CP_STG_SZ;

#pragma unroll
        for (int ks = 0; ks < 4; ks++) {
            uint32_t ahi[2][4], alo[2][4], bhi[5][2], blo[5][2];
            uint32_t ao = stg + aoff0 + ks * 32;
            ldsm4(ahi[0], ao + CP_A_HI);
            ldsm4(ahi[1], ao + CP_A_HI + 16 * 144);
            ldsm4(alo[0], ao + CP_A_LO);
            ldsm4(alo[1], ao + CP_A_LO + 16 * 144);
            uint32_t bo = stg + boff0 + ks * 32;
            uint32_t bo2 = stg + boff2 + ks * 32;
            ldsm4(&bhi[0][0], bo + CP_B_HI);
            ldsm4(&bhi[2][0], bo + CP_B_HI + 16 * 144);
            ldsm2(&bhi[4][0], bo2 + CP_B_HI);
            ldsm4(&blo[0][0], bo + CP_B_LO);
            ldsm4(&blo[2][0], bo + CP_B_LO + 16 * 144);
            ldsm2(&blo[4][0], bo2 + CP_B_LO);
#pragma unroll
            for (int mt = 0; mt < 2; mt++)
#pragma unroll
                for (int nt = 0; nt < 5; nt++) {
                    mma16816(acc[mt][nt], ahi[mt], bhi[nt]);
                    mma16816(acc[mt][nt], alo[mt], bhi[nt]);
                    mma16816(acc[mt][nt], ahi[mt], blo[nt]);
                }
        }
        __syncthreads();
        if (c + 2 < 64) load_chunk(c + 2, bsel);
        else cp_commit();
    }

    float* h1 = (float*)(smem + CP_STG0);
    int qrow = lane >> 2;
    int qcol = (lane & 3) * 2;
#pragma unroll
    for (int mt = 0; mt < 2; mt++)
#pragma unroll
        for (int i = 0; i < 2; i++) {
            int r = mw * 32 + mt * 16 + qrow + i * 8;
#pragma unroll
            for (int nt = 0; nt < 5; nt++)
#pragma unroll
                for (int j = 0; j < 2; j++) {
                    int col = nw * 40 + nt * 8 + qcol + j;
                    h1[r * 81 + col] = lrelu(acc[mt][nt][i * 2 + j] + __ldg(&bm0[col]));
                }
        }
    __syncthreads();

#pragma unroll 1
    for (int ii = 0; ii < 15; ii++) {
        int idx = tid + ii * 512;
        int m = idx & 127, o2 = idx >> 7;
        float a = __ldg(&bm1[o2]);
#pragma unroll 4
        for (int c4 = 0; c4 < 80; c4 += 4) {
            float4 wv = *(const float4*)&sW1[o2 * 80 + c4];
            a = fmaf(h1[m * 81 + c4 + 0], wv.x,
                fmaf(h1[m * 81 + c4 + 1], wv.y,
                fmaf(h1[m * 81 + c4 + 2], wv.z,
                fmaf(h1[m * 81 + c4 + 3], wv.w, a))));
        }
        long gm = m0 + m;
        if (gm < B) out[gm * 60 + o2] = lrelu(a);
    }
}

// ---------------------------------------------------------------------------
extern "C" void kernel_launch(void* const* d_in, const int* in_sizes, int n_in,
                              void* d_out, int out_size) {
    const float* x   = (const float*)d_in[0];
    const float* w0  = (const float*)d_in[1];
    const float* b0  = (const float*)d_in[2];
    const float* s0  = (const float*)d_in[3];
    const float* w1  = (const float*)d_in[4];
    const float* b1  = (const float*)d_in[5];
    const float* s1  = (const float*)d_in[6];
    const float* w2  = (const float*)d_in[7];
    const float* b2  = (const float*)d_in[8];
    const float* s2  = (const float*)d_in[9];
    const float* w3  = (const float*)d_in[10];
    const float* b3  = (const float*)d_in[11];
    const float* s3  = (const float*)d_in[12];
    const float* wm0 = (const float*)d_in[13];
    const float* bm0 = (const float*)d_in[14];
    const float* wm1 = (const float*)d_in[15];
    const float* bm1 = (const float*)d_in[16];

    int B = in_sizes[0] / 4096;
    if (B > MAXB) B = MAXB;

    cudaFuncSetAttribute((const void*)gauss_mma_kernel,
                         cudaFuncAttributeMaxDynamicSharedMemorySize, GM_SMEM);
    cudaFuncSetAttribute((const void*)compress_mma_kernel,
                         cudaFuncAttributeMaxDynamicSharedMemorySize, CP_SMEM_BYTES);

    kprep_kernel<<<1, 256>>>(s0, s1, s2, s3);
    wprep_kernel<<<160, 512>>>(wm0);
    gauss_mma_kernel<<<(B + 7) / 8, 512, GM_SMEM>>>(
        x, w0, b0, w1, b1, w2, b2, w3, b3, B);
    compress_mma_kernel<<<(B + 127) / 128, 512, CP_SMEM_BYTES>>>(
        bm0, wm1, bm1, (float*)d_out, B);
}